// round 4
// baseline (speedup 1.0000x reference)
#include <cuda_runtime.h>
#include <cuda_bf16.h>

#define T_DATA 4096
#define SUB 1024
#define NEG_L2E (-1.4426950408889634f)
#define WPB 4   // warps per block; grid = SUB/WPB = 256 blocks

__device__ __forceinline__ float ex2_(float x) {
    float y; asm("ex2.approx.f32 %0, %1;" : "=f"(y) : "f"(x)); return y;
}
__device__ __forceinline__ float rcp_(float x) {
    float y; asm("rcp.approx.f32 %0, %1;" : "=f"(y) : "f"(x)); return y;
}

// One warp per sub-unit. State per warp:
//   accA/accB: 64-slot systolic ring of pre-scaled X_in accumulators
//              (slot r lives in reg accA of lane r for r<32, accB of lane r-32).
//   G-domain: acc holds G = -log2e * X_in, so sigmoid = rcp(1 + ex2(G)).
// Per step t = base+i:
//   F[t] was broadcast LAST iteration (Fnext) -> sigmoid chain starts immediately.
//   All 32 lanes redundantly compute X,Z; scatter: each lane 2 FMAs into its
//   owned future slots with taps kern[(r-1-i)&63] (kern[0]==0 exactly, so the
//   "skip" tap is a harmless FMA with 0).
__global__ __launch_bounds__(WPB*32, 1)
void leaf_kernel(const float* __restrict__ S_conv,
                 const float* __restrict__ up_mu_Z,
                 const float* __restrict__ noise,
                 const float* __restrict__ W_sub,
                 const float* __restrict__ theta_syn,
                 const float* __restrict__ theta_spike,
                 const float* __restrict__ W_spike,
                 const float* __restrict__ tau_hist,
                 const float* __restrict__ K_hist,
                 const float* __restrict__ delta_hist,
                 float* __restrict__ out)
{
    __shared__ float sh_kern[WPB][64];
    __shared__ float sh_a[WPB][64];   // pre-scaled a[t] = -L2E*(s_t + theta_syn) for NEXT-chunk reinits
    __shared__ float sh_c[WPB][64];   // c[t] = -L2E*(0.5*up + n + 0.5*theta_spike), current chunk
    __shared__ float sh_u[WPB][64];   // 0.5*up_t, current chunk

    const int lane = threadIdx.x & 31;
    const int w    = threadIdx.x >> 5;
    const int unit = blockIdx.x * WPB + w;

    float* kernS = sh_kern[w];
    float* aC    = sh_a[w];
    float* cC    = sh_c[w];
    float* uC    = sh_u[w];

    const float th_syn = theta_syn[unit];
    const float th_spk = theta_spike[unit];
    const float Wspk   = W_spike[unit];
    const float Wsub   = W_sub[unit];
    const float delta  = delta_hist[unit];
    const float qc         = NEG_L2E * 0.5f * Wspk;   // G2 = qc*X + c[t]
    const float half_thspk = 0.5f * th_spk;

    // ---- kernel weights: kernS[j] = -L2E * sum_b ttau*exp(-ttau)*K_b ----
    {
        const float K0 = K_hist[unit*4+0];
        const float K1 = K_hist[unit*4+1];
        const float K2 = K_hist[unit*4+2];
        const float K3 = K_hist[unit*4+3];
        const float it0 = __expf(-tau_hist[0]);
        const float it1 = __expf(-tau_hist[1]);
        const float it2 = __expf(-tau_hist[2]);
        const float it3 = __expf(-tau_hist[3]);
        #pragma unroll
        for (int rr = 0; rr < 2; rr++) {
            const int j = lane + rr*32;
            const float tt = fmaxf((float)j - delta, 0.0f);
            const float x0 = tt*it0, x1 = tt*it1, x2 = tt*it2, x3 = tt*it3;
            float s = x0*__expf(-x0)*K0;
            s = fmaf(x1*__expf(-x1), K1, s);
            s = fmaf(x2*__expf(-x2), K2, s);
            s = fmaf(x3*__expf(-x3), K3, s);
            kernS[j] = NEG_L2E * s;   // kernS[0] == 0 exactly
        }
    }

    // ---- init ring with a[0..63] (zero history), aC with a[64..127],
    //      cC/uC with rows 0..63 ----
    float accA = NEG_L2E * (S_conv[lane*SUB + unit] + th_syn);
    float accB = NEG_L2E * (S_conv[(lane+32)*SUB + unit] + th_syn);
    aC[lane]    = NEG_L2E * (S_conv[(64+lane)*SUB + unit] + th_syn);
    aC[lane+32] = NEG_L2E * (S_conv[(96+lane)*SUB + unit] + th_syn);
    {
        const float u0 = up_mu_Z[lane*SUB+unit],      n0 = noise[lane*SUB+unit];
        const float u1 = up_mu_Z[(lane+32)*SUB+unit], n1 = noise[(lane+32)*SUB+unit];
        cC[lane]    = NEG_L2E * (fmaf(0.5f, u0, n0) + half_thspk);
        cC[lane+32] = NEG_L2E * (fmaf(0.5f, u1, n1) + half_thspk);
        uC[lane]    = 0.5f*u0;
        uC[lane+32] = 0.5f*u1;
    }
    __syncwarp();

    // slot 0 broadcast for step 0
    float Fnext = __shfl_sync(0xffffffffu, accA, 0);

    float* pY = out + unit;
    float* pZ = out + (size_t)T_DATA*SUB   + unit;
    float* pM = out + (size_t)2*T_DATA*SUB + unit;
    float* pD = out + (size_t)3*T_DATA*SUB + unit;

    for (int base = 0; base < T_DATA; base += 64) {
        // ---- prefetch next chunk's inputs (regs; STS at chunk end) ----
        const int nb = base + 64;
        float up0=0.f, up1=0.f, nz0=0.f, nz1=0.f, s0=0.f, s1=0.f;
        if (nb < T_DATA) {
            const int r0 = (nb + lane)*SUB + unit;
            up0 = up_mu_Z[r0]; up1 = up_mu_Z[r0 + 32*SUB];
            nz0 = noise[r0];   nz1 = noise[r0 + 32*SUB];
            const int r2 = nb + 64 + lane;
            if (r2 < T_DATA)      s0 = S_conv[r2*SUB + unit];
            if (r2 + 32 < T_DATA) s1 = S_conv[(r2+32)*SUB + unit];
        }

        #pragma unroll
        for (int i = 0; i < 64; i++) {
            // early, off-critical-path loads (all static shared addresses)
            const float kA = kernS[(lane - 1 - i) & 63];
            const float kB = kernS[(lane + 31 - i) & 63];
            const float cc = cC[i];
            const float av = aC[i];

            const float F = Fnext;

            // reinit the just-consumed slot i with a[base+64+i]
            if ((i & 32) == 0) { if (lane == i)        accA = av; }
            else               { if (lane == (i & 31)) accB = av; }

            // broadcast slot i+1 (complete: its last real tap used Z_{t-1},
            // applied in the previous iteration's scatter; kern[0]==0)
            {
                const int nx = (i + 1) & 63;
                const float src = (nx & 32) ? accB : accA;
                Fnext = __shfl_sync(0xffffffffu, src, nx & 31);
            }

            // sigmoid chain (all lanes redundantly -> Z available everywhere)
            const float X = rcp_(1.0f + ex2_(F));
            const float Z = rcp_(1.0f + ex2_(fmaf(qc, X, cc)));

            if (lane == 0) {
                const float uu = uC[i];
                const float Y  = X * Wsub;
                const float dn = fmaf(X, Wspk, th_spk);
                const float mu = fmaf(0.5f, dn, uu);
                pY[i*SUB] = Y;
                pZ[i*SUB] = Z;
                pM[i*SUB] = mu;
                pD[i*SUB] = dn;
            }

            // systolic scatter: 2 FMAs per lane into owned future slots
            accA = fmaf(kA, Z, accA);
            accB = fmaf(kB, Z, accB);
        }

        // ---- publish next chunk's shared data ----
        __syncwarp();
        cC[lane]    = NEG_L2E * (fmaf(0.5f, up0, nz0) + half_thspk);
        cC[lane+32] = NEG_L2E * (fmaf(0.5f, up1, nz1) + half_thspk);
        uC[lane]    = 0.5f*up0;
        uC[lane+32] = 0.5f*up1;
        aC[lane]    = NEG_L2E * (s0 + th_syn);
        aC[lane+32] = NEG_L2E * (s1 + th_syn);
        __syncwarp();

        pY += 64*SUB; pZ += 64*SUB; pM += 64*SUB; pD += 64*SUB;
    }
}

extern "C" void kernel_launch(void* const* d_in, const int* in_sizes, int n_in,
                              void* d_out, int out_size) {
    (void)in_sizes; (void)n_in; (void)out_size;
    leaf_kernel<<<SUB/WPB, WPB*32>>>(
        (const float*)d_in[0],  // S_conv
        (const float*)d_in[1],  // up_mu_Z
        (const float*)d_in[2],  // noise
        (const float*)d_in[3],  // W_sub
        (const float*)d_in[4],  // theta_syn
        (const float*)d_in[5],  // theta_spike
        (const float*)d_in[6],  // W_spike
        (const float*)d_in[7],  // tau_hist
        (const float*)d_in[8],  // K_hist
        (const float*)d_in[9],  // delta_hist
        (float*)d_out);
}

// round 6
// speedup vs baseline: 1.3611x; 1.3611x over previous
#include <cuda_runtime.h>
#include <cuda_bf16.h>

#define T_DATA 4096
#define SUB 1024
#define WPB 4   // warps per block; grid = SUB/WPB = 256 blocks

__device__ __forceinline__ float tanh_(float x) {
    float y; asm("tanh.approx.f32 %0, %1;" : "=f"(y) : "f"(x)); return y;
}

// One warp per sub-unit. Ring accA/accB: 64 slots of h = X_in/2 partial sums
// (slot r: accA lane r for r<32, else accB lane r-32). sigmoid(x)=0.5+0.5*tanh(x/2).
// Software-pipelined: iteration i computes step i's tanh chain at the HEAD
// (depends only on Z_{i-2} via F_i = fma(k1h, Z_{i-2}, P_i)), and defers step
// i-1's reinit+scatter to the TAIL. P_{i+2} (slot value missing only the j<=1
// taps) is shfl'd at the tail -> SHFL and scatter are off the critical path.
// Outputs are not computed in the loop: {v1,v2} go to shared, a per-chunk
// flush phase does the 4 output arrays with all 32 lanes.
__global__ __launch_bounds__(WPB*32, 1)
void leaf_kernel(const float* __restrict__ S_conv,
                 const float* __restrict__ up_mu_Z,
                 const float* __restrict__ noise,
                 const float* __restrict__ W_sub,
                 const float* __restrict__ theta_syn,
                 const float* __restrict__ theta_spike,
                 const float* __restrict__ W_spike,
                 const float* __restrict__ tau_hist,
                 const float* __restrict__ K_hist,
                 const float* __restrict__ delta_hist,
                 float* __restrict__ out)
{
    __shared__ float sh_kq[WPB][128];                 // 0.5*kern, duplicated [j] and [j+64]
    __shared__ float sh_a[WPB][64];                   // 0.5*(s_t+th_syn) for NEXT chunk reinits
    __shared__ float sh_c[WPB][64];                   // c2[t] = 0.25*up + 0.5*n + c2const
    __shared__ __align__(16) float sh_u[WPB][64];     // 0.5*up_t (float2-read in flush)
    __shared__ __align__(16) float sh_v[WPB][64][2];  // {v1,v2} per step

    const int lane = threadIdx.x & 31;
    const int w    = threadIdx.x >> 5;
    const int unit = blockIdx.x * WPB + w;

    float* kq = sh_kq[w];
    float* aC = sh_a[w];
    float* cC = sh_c[w];
    float* uC = sh_u[w];
    float (*vv)[2] = sh_v[w];

    const float th_syn = theta_syn[unit];
    const float th_spk = theta_spike[unit];
    const float Wspk   = W_spike[unit];
    const float Wsub   = W_sub[unit];
    const float delta  = delta_hist[unit];
    const float q2      = 0.125f * Wspk;               // g2 = q2*v1 + c2[t]
    const float c2const = 0.25f * th_spk + 0.125f * Wspk;

    // ---- taps: kq[j] = kq[j+64] = 0.5 * sum_b ttau*exp(-ttau)*K_b ; kq[64]==0 exactly ----
    {
        const float K0 = K_hist[unit*4+0];
        const float K1 = K_hist[unit*4+1];
        const float K2 = K_hist[unit*4+2];
        const float K3 = K_hist[unit*4+3];
        const float it0 = __expf(-tau_hist[0]);
        const float it1 = __expf(-tau_hist[1]);
        const float it2 = __expf(-tau_hist[2]);
        const float it3 = __expf(-tau_hist[3]);
        #pragma unroll
        for (int rr = 0; rr < 2; rr++) {
            const int j = lane + rr*32;
            const float tt = fmaxf((float)j - delta, 0.0f);
            const float x0 = tt*it0, x1 = tt*it1, x2 = tt*it2, x3 = tt*it3;
            float s = x0*__expf(-x0)*K0;
            s = fmaf(x1*__expf(-x1), K1, s);
            s = fmaf(x2*__expf(-x2), K2, s);
            s = fmaf(x3*__expf(-x3), K3, s);
            kq[j]      = 0.5f * s;
            kq[j + 64] = 0.5f * s;
        }
    }

    // ---- init ring (h-domain, zero history): slot t = 0.5*(s_t+th_syn), t=0..63 ----
    float accA = 0.5f * (S_conv[lane*SUB + unit] + th_syn);
    float accB = 0.5f * (S_conv[(lane+32)*SUB + unit] + th_syn);
    aC[lane]    = 0.5f * (S_conv[(64+lane)*SUB + unit] + th_syn);
    aC[lane+32] = 0.5f * (S_conv[(96+lane)*SUB + unit] + th_syn);
    {
        const float u0 = up_mu_Z[lane*SUB+unit],      n0 = noise[lane*SUB+unit];
        const float u1 = up_mu_Z[(lane+32)*SUB+unit], n1 = noise[(lane+32)*SUB+unit];
        cC[lane]    = fmaf(0.25f, u0, fmaf(0.5f, n0, c2const));
        cC[lane+32] = fmaf(0.25f, u1, fmaf(0.5f, n1, c2const));
        uC[lane]    = 0.5f*u0;
        uC[lane+32] = 0.5f*u1;
    }
    __syncwarp();

    const float k1h = kq[1];   // 0.5*kern[1]

    // pipeline state
    float Zm1 = 0.0f, Zm2 = 0.0f;
    float Pc   = __shfl_sync(0xffffffffu, accA, 0);   // P for step 0 (= a_half[0])
    float Pn   = __shfl_sync(0xffffffffu, accA, 1);   // P for step 1
    float avm1 = __shfl_sync(0xffffffffu, accB, 31);  // no-op reinit value for iter 0 (slot 63)

    // per-lane store bases: lane handles steps 2*lane, 2*lane+1 in flush
    float* pY = out + (size_t)0*T_DATA*SUB + (size_t)2*lane*SUB + unit;
    float* pZ = out + (size_t)1*T_DATA*SUB + (size_t)2*lane*SUB + unit;
    float* pM = out + (size_t)2*T_DATA*SUB + (size_t)2*lane*SUB + unit;
    float* pD = out + (size_t)3*T_DATA*SUB + (size_t)2*lane*SUB + unit;

    for (int base = 0; base < T_DATA; base += 64) {
        // ---- prefetch next chunk inputs into regs ----
        const int nb = base + 64;
        float up0=0.f, up1=0.f, nz0=0.f, nz1=0.f, s0=0.f, s1=0.f;
        if (nb < T_DATA) {
            const int r0 = (nb + lane)*SUB + unit;
            up0 = up_mu_Z[r0]; up1 = up_mu_Z[r0 + 32*SUB];
            nz0 = noise[r0];   nz1 = noise[r0 + 32*SUB];
            const int r2 = nb + 64 + lane;
            if (r2 < T_DATA)      s0 = S_conv[r2*SUB + unit];
            if (r2 + 32 < T_DATA) s1 = S_conv[(r2+32)*SUB + unit];
        }

        #pragma unroll
        for (int i = 0; i < 64; i++) {
            // off-path loads
            const float cc = cC[i];
            const float av = aC[i];            // reinit value for slot i, used next iter
            const float kA = kq[64 + lane - i];  // tap for step i-1 scatter, accA
            const float kB = kq[96 + lane - i];  // tap for step i-1 scatter, accB

            // ---- head: step i (depends only on Z_{i-2}) ----
            const float F  = fmaf(k1h, Zm2, Pc);
            const float v1 = tanh_(F);
            const float g2 = fmaf(q2, v1, cc);
            const float v2 = tanh_(g2);
            const float Z  = fmaf(0.5f, v2, 0.5f);
            *(float2*)&vv[i][0] = make_float2(v1, v2);  // STS.64, uniform addr

            // ---- tail: step i-1 (reinit slot i-1, then scatter Z_{i-1}) ----
            {
                const int s = (i - 1) & 63;   // compile-time
                if (s < 32) { if (lane == s)        accA = avm1; }
                else        { if (lane == (s-32))   accB = avm1; }
            }
            accA = fmaf(kA, Zm1, accA);
            accB = fmaf(kB, Zm1, accB);

            // ---- shfl partial P for step i+2 (after step i-1's scatter) ----
            Pc = Pn;
            {
                const int nx = (i + 2) & 63;  // compile-time
                const float src = (nx & 32) ? accB : accA;
                Pn = __shfl_sync(0xffffffffu, src, nx & 31);
            }

            // rotate
            Zm2 = Zm1; Zm1 = Z; avm1 = av;
        }

        // ---- flush: outputs for steps base..base+63, 2 steps per lane ----
        __syncwarp();
        {
            const float4 vq = *(const float4*)(&vv[2*lane][0]);  // v1a,v2a,v1b,v2b
            const float2 uq = *(const float2*)(&uC[2*lane]);
            const float Xa = fmaf(0.5f, vq.x, 0.5f);
            const float Za = fmaf(0.5f, vq.y, 0.5f);
            const float Ya = Xa * Wsub;
            const float da = fmaf(Xa, Wspk, th_spk);
            const float ma = fmaf(0.5f, da, uq.x);
            const float Xb = fmaf(0.5f, vq.z, 0.5f);
            const float Zb = fmaf(0.5f, vq.w, 0.5f);
            const float Yb = Xb * Wsub;
            const float db = fmaf(Xb, Wspk, th_spk);
            const float mb = fmaf(0.5f, db, uq.y);
            pY[0] = Ya; pY[SUB] = Yb;
            pZ[0] = Za; pZ[SUB] = Zb;
            pM[0] = ma; pM[SUB] = mb;
            pD[0] = da; pD[SUB] = db;
        }
        __syncwarp();

        // ---- publish next chunk shared data ----
        cC[lane]    = fmaf(0.25f, up0, fmaf(0.5f, nz0, c2const));
        cC[lane+32] = fmaf(0.25f, up1, fmaf(0.5f, nz1, c2const));
        uC[lane]    = 0.5f*up0;
        uC[lane+32] = 0.5f*up1;
        aC[lane]    = 0.5f * (s0 + th_syn);
        aC[lane+32] = 0.5f * (s1 + th_syn);
        __syncwarp();

        pY += 64*SUB; pZ += 64*SUB; pM += 64*SUB; pD += 64*SUB;
    }
}

extern "C" void kernel_launch(void* const* d_in, const int* in_sizes, int n_in,
                              void* d_out, int out_size) {
    (void)in_sizes; (void)n_in; (void)out_size;
    leaf_kernel<<<SUB/WPB, WPB*32>>>(
        (const float*)d_in[0],  // S_conv
        (const float*)d_in[1],  // up_mu_Z
        (const float*)d_in[2],  // noise
        (const float*)d_in[3],  // W_sub
        (const float*)d_in[4],  // theta_syn
        (const float*)d_in[5],  // theta_spike
        (const float*)d_in[6],  // W_spike
        (const float*)d_in[7],  // tau_hist
        (const float*)d_in[8],  // K_hist
        (const float*)d_in[9],  // delta_hist
        (float*)d_out);
}

// round 10
// speedup vs baseline: 2.3155x; 1.7012x over previous
#include <cuda_runtime.h>
#include <cuda_bf16.h>

#define T_DATA 4096
#define SUB 1024
#define WPB 8   // warps per block; grid = SUB/WPB = 128 blocks
#define TS ((size_t)T_DATA * SUB)

__device__ __forceinline__ float tanh_(float x) {
    float y; asm("tanh.approx.f32 %0, %1;" : "=f"(y) : "f"(x)); return y;
}

// One warp per sub-unit; 8 units per block. 64-slot systolic ring in accA/accB
// (h-domain: 0.5*X_in). sigmoid(x) = 0.5 + 0.5*tanh(x/2); kern[0] == 0 so
// Z_t depends on Z_{t-2} -> steps processed in PAIRS with the two tanh chains
// explicitly interleaved (both depend only on the previous pair).
// P lookahead: even step P misses j<=1 taps (head adds k1*Z_{t-2});
// odd step P misses j<=2 taps (head adds k1*Z_{t-2} + k2*Z_{t-3}); both
// P-shfls therefore depend only on the Zb (prev-pair) scatter -> no exposed
// SHFL latency. Global I/O is block-cooperative and coalesced via shared tiles.
__global__ __launch_bounds__(WPB*32, 1)
void leaf_kernel(const float* __restrict__ S_conv,
                 const float* __restrict__ up_mu_Z,
                 const float* __restrict__ noise,
                 const float* __restrict__ W_sub,
                 const float* __restrict__ theta_syn,
                 const float* __restrict__ theta_spike,
                 const float* __restrict__ W_spike,
                 const float* __restrict__ tau_hist,
                 const float* __restrict__ K_hist,
                 const float* __restrict__ delta_hist,
                 float* __restrict__ out)
{
    __shared__ __align__(16) float sh_kq[WPB][128];   // 0.5*kern, duplicated [j],[j+64]
    __shared__ __align__(16) float sh_a[WPB][66];     // 0.5*(s+th_syn), reinit values (pad 66)
    __shared__ __align__(16) float sh_c[WPB][66];     // 0.25*up + 0.5*n + c2const
    __shared__ __align__(16) float sh_u[64][WPB];     // 0.5*up  (flush only)
    __shared__ __align__(16) float sh_v[64][WPB][2];  // {v1,v2} per step per unit

    const int tid  = threadIdx.x;
    const int lane = tid & 31;
    const int w    = tid >> 5;
    const int u0   = blockIdx.x * WPB;
    const int unit = u0 + w;
    const bool isl0 = (lane == 0);

    float* kq = sh_kq[w];

    // per-warp unit constants
    const float th_syn = theta_syn[unit];
    const float Wspk   = W_spike[unit];
    const float delta  = delta_hist[unit];
    const float q2     = 0.125f * Wspk;

    // per-thread column constants (for cooperative staging + flush)
    const int  col    = tid & 7;
    const int  row0   = tid >> 3;        // 0..31
    const int  ucol   = u0 + col;
    const float thsyn_c = theta_syn[ucol];
    const float thspk_c = theta_spike[ucol];
    const float wspk_c  = W_spike[ucol];
    const float wsub_c  = W_sub[ucol];
    const float c2c_c   = 0.25f * thspk_c + 0.125f * wspk_c;

    // ---- taps: kq[j] = kq[j+64] = 0.5 * sum_b ttau*exp(-ttau)*K_b ; kq[0]==0 ----
    {
        const float K0 = K_hist[unit*4+0];
        const float K1 = K_hist[unit*4+1];
        const float K2 = K_hist[unit*4+2];
        const float K3 = K_hist[unit*4+3];
        const float it0 = __expf(-tau_hist[0]);
        const float it1 = __expf(-tau_hist[1]);
        const float it2 = __expf(-tau_hist[2]);
        const float it3 = __expf(-tau_hist[3]);
        #pragma unroll
        for (int rr = 0; rr < 2; rr++) {
            const int j = lane + rr*32;
            const float tt = fmaxf((float)j - delta, 0.0f);
            const float x0 = tt*it0, x1 = tt*it1, x2 = tt*it2, x3 = tt*it3;
            float s = x0*__expf(-x0)*K0;
            s = fmaf(x1*__expf(-x1), K1, s);
            s = fmaf(x2*__expf(-x2), K2, s);
            s = fmaf(x3*__expf(-x3), K3, s);
            kq[j]      = 0.5f * s;
            kq[j + 64] = 0.5f * s;
        }
    }

    // ---- ring init: slot t = 0.5*(s_t + th_syn), t = 0..63 (one-time strided LDG) ----
    float accA = 0.5f * (S_conv[(size_t)lane*SUB + unit] + th_syn);
    float accB = 0.5f * (S_conv[(size_t)(lane+32)*SUB + unit] + th_syn);
    __syncwarp();

    const float k1h = kq[1];
    const float k2h = kq[2];

    // ---- initial cooperative staging: c/u rows 0..63, a rows 64..127 ----
    #pragma unroll
    for (int rr = 0; rr < 2; rr++) {
        const int row = row0 + rr*32;
        const size_t idx = (size_t)row*SUB + ucol;
        const float up = up_mu_Z[idx];
        const float nz = noise[idx];
        sh_c[col][row] = fmaf(0.25f, up, fmaf(0.5f, nz, c2c_c));
        sh_u[row][col] = 0.5f * up;
        sh_a[col][row] = 0.5f * (S_conv[(size_t)(64+row)*SUB + ucol] + thsyn_c);
    }

    // pipeline bootstrap
    float Za = 0.0f, Zb = 0.0f;                        // Z_{-2}, Z_{-1}
    float Pa = __shfl_sync(0xffffffffu, accA, 0);      // P_0 (j>=2 taps: none yet)
    float Pb = __shfl_sync(0xffffffffu, accA, 1);      // P'_1 (j>=3 taps: none yet)
    float av_prev = __shfl_sync(0xffffffffu, accB, 31); // no-op reinit for slot 63 at pair 0

    __syncthreads();

    for (int base = 0; base < T_DATA; base += 64) {
        #pragma unroll
        for (int i = 0; i < 64; i += 2) {
            const float2 ccp = *(const float2*)&sh_c[w][i];
            const float2 avp = *(const float2*)&sh_a[w][i];
            const float kA0 = kq[64 + lane - i];
            const float kB0 = kq[96 + lane - i];
            const float kA1 = kq[63 + lane - i];
            const float kB1 = kq[95 + lane - i];

            // ---- head: steps t0=base+i, t1=t0+1; chains depend only on prev pair ----
            const float F0  = fmaf(k1h, Za, Pa);
            const float F1  = fmaf(k1h, Zb, fmaf(k2h, Za, Pb));
            const float v10 = tanh_(F0);
            const float v11 = tanh_(F1);
            const float g0  = fmaf(q2, v10, ccp.x);
            const float g1  = fmaf(q2, v11, ccp.y);
            const float v20 = tanh_(g0);
            const float v21 = tanh_(g1);
            const float Z0  = fmaf(0.5f, v20, 0.5f);
            const float Z1  = fmaf(0.5f, v21, 0.5f);
            if (isl0) {
                *(float2*)&sh_v[i][w][0]   = make_float2(v10, v20);
                *(float2*)&sh_v[i+1][w][0] = make_float2(v11, v21);
            }

            // ---- tail ----
            // reinit slot (i-1)&63 (value a[base+64+i-1], no-op at very first pair)
            {
                const int s = (i - 1) & 63;
                if (s < 32) { if (lane == s)      accA = av_prev; }
                else        { if (lane == s - 32) accB = av_prev; }
            }
            // reinit slot i (value a[base+64+i])
            {
                if (i < 32) { if (lane == i)      accA = avp.x; }
                else        { if (lane == i - 32) accB = avp.x; }
            }
            // scatter Zb = Z_{t0-1} (wheel i); slot i gets kern[0]==0 (harmless)
            accA = fmaf(kA0, Zb, accA);
            accB = fmaf(kB0, Zb, accB);
            // both P-shfls depend only on the Zb scatter (slack = full pair)
            {
                const int nx = (i + 2) & 63;
                Pa = __shfl_sync(0xffffffffu, (nx & 32) ? accB : accA, nx & 31);
            }
            {
                const int nx = (i + 3) & 63;
                Pb = __shfl_sync(0xffffffffu, (nx & 32) ? accB : accA, nx & 31);
            }
            // scatter Z0 = Z_{t0} (wheel i+1); post-shfl taps land in dead slots
            accA = fmaf(kA1, Z0, accA);
            accB = fmaf(kB1, Z0, accB);

            Za = Z0; Zb = Z1; av_prev = avp.y;
        }

        __syncthreads();

        // ---- flush: coalesced outputs for this chunk (4 sectors per STG) ----
        #pragma unroll
        for (int rr = 0; rr < 2; rr++) {
            const int row = row0 + rr*32;
            const float2 v = *(const float2*)&sh_v[row][col][0];
            const float uu = sh_u[row][col];
            const float X  = fmaf(0.5f, v.x, 0.5f);
            const float Z  = fmaf(0.5f, v.y, 0.5f);
            const float Y  = X * wsub_c;
            const float dn = fmaf(X, wspk_c, thspk_c);
            const float mu = fmaf(0.5f, dn, uu);
            const size_t o = (size_t)(base + row)*SUB + ucol;
            out[o]        = Y;
            out[TS + o]   = Z;
            out[2*TS + o] = mu;
            out[3*TS + o] = dn;
        }

        // ---- stage next chunk (coalesced) ----
        const int nb = base + 64;
        if (nb < T_DATA) {
            #pragma unroll
            for (int rr = 0; rr < 2; rr++) {
                const int row = row0 + rr*32;
                const size_t idx = (size_t)(nb + row)*SUB + ucol;
                const float up = up_mu_Z[idx];
                const float nz = noise[idx];
                sh_c[col][row] = fmaf(0.25f, up, fmaf(0.5f, nz, c2c_c));
                sh_u[row][col] = 0.5f * up;
                const int ar = nb + 64 + row;
                sh_a[col][row] = (ar < T_DATA)
                    ? 0.5f * (S_conv[(size_t)ar*SUB + ucol] + thsyn_c) : 0.0f;
            }
        }
        __syncthreads();
    }
}

extern "C" void kernel_launch(void* const* d_in, const int* in_sizes, int n_in,
                              void* d_out, int out_size) {
    (void)in_sizes; (void)n_in; (void)out_size;
    leaf_kernel<<<SUB/WPB, WPB*32>>>(
        (const float*)d_in[0],  // S_conv
        (const float*)d_in[1],  // up_mu_Z
        (const float*)d_in[2],  // noise
        (const float*)d_in[3],  // W_sub
        (const float*)d_in[4],  // theta_syn
        (const float*)d_in[5],  // theta_spike
        (const float*)d_in[6],  // W_spike
        (const float*)d_in[7],  // tau_hist
        (const float*)d_in[8],  // K_hist
        (const float*)d_in[9],  // delta_hist
        (float*)d_out);
}